// round 5
// baseline (speedup 1.0000x reference)
#include <cuda_runtime.h>
#include <cuda_fp16.h>
#include <cstdint>
#include <cstddef>

#define DINL __device__ __forceinline__

// Problem: B=32, T=2048, H=1024
// inputs: 0 enc[32,2048,1024] f32, 1 dec[1,32,1024] f32, 2 Wk[1024,1024] f32,
//         3 bk[1024], 4 Wq[1024,1024], 5 bq[1024], 6 Wout[1024], 7 bout, 8 inputs(unused)
// out: [32,1,1024] f32

// ======================= static device scratch =======================
// enc fp16 tiles: [mt 0..511][kc 0..15] each 128 rows x 64 k-cols, SW128, 16 KB
__device__ __align__(1024) unsigned char g_encb[512ull * 16ull * 16384ull];  // 128 MB
// Wk fp16 tiles: [kc 0..15][ncB 0..7] each 128 n-rows x 64 k-cols, SW128, 16 KB
__device__ __align__(1024) unsigned char g_wkb[16ull * 8ull * 16384ull];     // 2 MB
__device__ float g_cbias[32 * 1024];
__device__ float g_scores[32 * 2048];
__device__ int g_flags[512];

// ======================= PTX helpers =======================
DINL unsigned smem_u32(const void* p) {
    unsigned a;
    asm("{ .reg .u64 t; cvta.to.shared.u64 t, %1; cvt.u32.u64 %0, t; }" : "=r"(a) : "l"(p));
    return a;
}

#define MBAR_INIT(a, c) \
    asm volatile("mbarrier.init.shared.b64 [%0], %1;" :: "r"(a), "r"(c) : "memory")
#define MBAR_EXPECT(a, b) \
    asm volatile("mbarrier.arrive.expect_tx.shared.b64 _, [%0], %1;" :: "r"(a), "r"(b) : "memory")
#define MBAR_ARRIVE(a) \
    asm volatile("mbarrier.arrive.shared.b64 _, [%0];" :: "r"(a) : "memory")

DINL void mbar_wait(unsigned mbar, unsigned parity) {
    asm volatile(
        "{\n\t"
        ".reg .pred P;\n\t"
        "WL_%=:\n\t"
        "mbarrier.try_wait.parity.acquire.cta.shared::cta.b64 P, [%0], %1, 0x989680;\n\t"
        "@P bra.uni WD_%=;\n\t"
        "bra.uni WL_%=;\n\t"
        "WD_%=:\n\t"
        "}"
        :: "r"(mbar), "r"(parity) : "memory");
}

DINL void bulk_g2s(unsigned dst, const void* src, unsigned bytes, unsigned mbar) {
    asm volatile(
        "cp.async.bulk.shared::cluster.global.mbarrier::complete_tx::bytes [%0], [%1], %2, [%3];"
        :: "r"(dst), "l"(src), "r"(bytes), "r"(mbar) : "memory");
}

DINL void ldsm_x4(unsigned& r0, unsigned& r1, unsigned& r2, unsigned& r3, unsigned addr) {
    asm volatile("ldmatrix.sync.aligned.m8n8.x4.shared.b16 {%0,%1,%2,%3}, [%4];"
                 : "=r"(r0), "=r"(r1), "=r"(r2), "=r"(r3) : "r"(addr));
}

DINL void mma16816(float* d, unsigned a0, unsigned a1, unsigned a2, unsigned a3,
                   unsigned b0, unsigned b1) {
    asm volatile(
        "mma.sync.aligned.m16n8k16.row.col.f32.f16.f16.f32 "
        "{%0,%1,%2,%3},{%4,%5,%6,%7},{%8,%9},{%0,%1,%2,%3};"
        : "+f"(d[0]), "+f"(d[1]), "+f"(d[2]), "+f"(d[3])
        : "r"(a0), "r"(a1), "r"(a2), "r"(a3), "r"(b0), "r"(b1));
}

DINL float tanh_fast(float x) {
    float t;
    asm("tanh.approx.f32 %0, %1;" : "=f"(t) : "f"(x));
    return t;
}

DINL void red_add(float* p, float v) {
    asm volatile("red.global.add.f32 [%0], %1;" :: "l"(p), "f"(v) : "memory");
}

DINL unsigned sw128(unsigned off) { return off ^ ((off >> 3) & 0x70); }

DINL unsigned pkh2(float a, float b) {
    __half ha = __float2half_rn(a), hb = __float2half_rn(b);
    return ((unsigned)__half_as_ushort(hb) << 16) | (unsigned)__half_as_ushort(ha);
}

// convert one enc M-tile (128 rows x 1024 cols f32) into 16 swizzled fp16 slabs.
// 256 threads cooperate. Deterministic pure function of input -> racing duplicate
// conversions write identical bytes (benign).
DINL void convert_tile(const float* __restrict__ enc, int mt, int tid) {
    const float* src = enc + (size_t)mt * 128 * 1024;
    unsigned char* dst = g_encb + (size_t)mt * 262144;
    for (int i = tid; i < 128 * 128; i += 256) {   // row x col-block(8)
        int r = i >> 7;
        int col = (i & 127) * 8;
        float4 f0 = *reinterpret_cast<const float4*>(src + (size_t)r * 1024 + col);
        float4 f1 = *reinterpret_cast<const float4*>(src + (size_t)r * 1024 + col + 4);
        uint4 v = make_uint4(pkh2(f0.x, f0.y), pkh2(f0.z, f0.w),
                             pkh2(f1.x, f1.y), pkh2(f1.z, f1.w));
        int kc = col >> 6;
        int c = col & 63;
        unsigned off = sw128((unsigned)(r * 128 + c * 2));
        *reinterpret_cast<uint4*>(dst + (size_t)kc * 16384 + off) = v;
    }
}

// ======================= kernel 1: prep = conv_wk + zero scores/flags + cbias =======================
// grid 4160: blocks 0..63 do Wk conversion + zeroing; blocks 64..4159 do cbias.
__global__ void __launch_bounds__(256) prep_kernel(const float* __restrict__ Wk,
                                                   const float* __restrict__ dec,
                                                   const float* __restrict__ Wq,
                                                   const float* __restrict__ bq,
                                                   const float* __restrict__ bk) {
    const int bx = blockIdx.x, tid = threadIdx.x;
    if (bx < 64) {
        // zero scores (64*256*4 = 65536 floats) and flags (64*8 = 512)
        int zi = bx * 256 + tid;
        *reinterpret_cast<float4*>(g_scores + zi * 4) = make_float4(0.f, 0.f, 0.f, 0.f);
        if (tid < 8) g_flags[bx * 8 + tid] = 0;

        for (int u = bx * 256 + tid; u < 1024 * 128; u += 64 * 256) {
            int h = u >> 7;
            int col = (u & 127) * 8;
            float4 f0 = *reinterpret_cast<const float4*>(Wk + (size_t)h * 1024 + col);
            float4 f1 = *reinterpret_cast<const float4*>(Wk + (size_t)h * 1024 + col + 4);
            uint4 v = make_uint4(pkh2(f0.x, f0.y), pkh2(f0.z, f0.w),
                                 pkh2(f1.x, f1.y), pkh2(f1.z, f1.w));
            int kc = col >> 6;
            int c = col & 63;
            int ncB = h >> 7;
            int nr = h & 127;
            unsigned off = sw128((unsigned)(nr * 128 + c * 2));
            *reinterpret_cast<uint4*>(g_wkb + ((size_t)kc * 8 + ncB) * 16384 + off) = v;
        }
    } else {
        // cbias[b,h] = dec[b]·Wq[h] + bq[h] + bk[h]
        int gw = (bx - 64) * 8 + (tid >> 5);
        int lane = tid & 31;
        int b = gw >> 10;
        int h = gw & 1023;
        float acc = 0.f;
#pragma unroll
        for (int it = 0; it < 8; it++) {
            int j = it * 128 + lane * 4;
            float4 d = *reinterpret_cast<const float4*>(dec + (size_t)b * 1024 + j);
            float4 w = *reinterpret_cast<const float4*>(Wq + (size_t)h * 1024 + j);
            acc += d.x * w.x + d.y * w.y + d.z * w.z + d.w * w.w;
        }
#pragma unroll
        for (int o = 16; o > 0; o >>= 1) acc += __shfl_down_sync(0xFFFFFFFFu, acc, o);
        if (lane == 0) g_cbias[b * 1024 + h] = acc + bq[h] + bk[h];
    }
}

// ======================= kernel 2: fused conv(A) + fp16 HMMA GEMM + tanh/Wout score =======================
// CTA tile: M=128, N=128, K=1024. grid 4096: mt = bx>>3, nc = bx&7.
// nc==0 CTA converts its enc M-tile to fp16 slabs first (flag release);
// siblings spin on the flag (bounded; self-convert fallback -> deadlock-proof).
// Mainloop = R3 structure (rolled, per-thread empty arrives) which measured 325us.
#define NST 3
#define SMEM_GEMM 98432
__global__ void __launch_bounds__(256, 2) gemm_score_kernel(const float* __restrict__ enc,
                                                            const float* __restrict__ Wout) {
    extern __shared__ __align__(128) unsigned char smem[];
    const unsigned sb = smem_u32(smem);
    const unsigned OFF_FULL = 98304, OFF_EMPTY = 98336;

    const int tid = threadIdx.x, wid = tid >> 5, lane = tid & 31;
    const int wr = wid >> 1;          // warp row 0..3  -> rows wr*32..+32
    const int wc = wid & 1;           // warp col 0..1  -> cols wc*64..+64
    const int mt = blockIdx.x >> 3;
    const int nc = blockIdx.x & 7;
    const int b = mt >> 4;

    if (tid == 0) {
#pragma unroll
        for (int s = 0; s < NST; s++) {
            MBAR_INIT(sb + OFF_FULL + s * 8, 1);
            MBAR_INIT(sb + OFF_EMPTY + s * 8, 256);
        }
        asm volatile("fence.proxy.async.shared::cta;" ::: "memory");
    }
    __syncthreads();

    // ---- A-tile conversion / readiness ----
    __shared__ int s_ok;
    if (nc == 0) {
        convert_tile(enc, mt, tid);
        __threadfence();
        __syncthreads();
        if (tid == 0) atomicExch(&g_flags[mt], 1);
    } else {
        if (tid == 0) {
            int ok = 0;
            for (int p = 0; p < 4096; p++) {
                if (*(volatile int*)&g_flags[mt]) { ok = 1; break; }
                __nanosleep(128);
            }
            s_ok = ok;
        }
        __syncthreads();
        if (!s_ok) {           // fallback: self-convert (identical-byte writes, benign race)
            convert_tile(enc, mt, tid);
            __threadfence();
            __syncthreads();
        }
    }

    const unsigned char* gA = g_encb + (size_t)mt * 262144;        // + kc*16384
    const unsigned char* gB0 = g_wkb + (size_t)nc * 16384;         // + kc*8*16384

    // prologue: fill all stages
    if (tid == 0) {
#pragma unroll
        for (int s = 0; s < NST; s++) {
            MBAR_EXPECT(sb + OFF_FULL + s * 8, 32768);
            bulk_g2s(sb + s * 32768, gA + (size_t)s * 16384, 16384, sb + OFF_FULL + s * 8);
            bulk_g2s(sb + s * 32768 + 16384, gB0 + (size_t)s * 131072, 16384,
                     sb + OFF_FULL + s * 8);
        }
    }

    float acc[2][8][4];
#pragma unroll
    for (int mf = 0; mf < 2; mf++)
#pragma unroll
        for (int nf = 0; nf < 8; nf++)
#pragma unroll
            for (int e = 0; e < 4; e++) acc[mf][nf][e] = 0.f;

    int phF0 = 0, phF1 = 0, phF2 = 0, phE0 = 0, phE1 = 0, phE2 = 0;
    const int l15 = lane & 15;
    const int lhi = lane >> 4;

#pragma unroll 1
    for (int k = 0; k < 16; k++) {
        const int st = k % NST;
        const unsigned fullb = sb + OFF_FULL + st * 8;
        const unsigned emptyb = sb + OFF_EMPTY + st * 8;
        int phF = (st == 0) ? phF0 : (st == 1) ? phF1 : phF2;
        mbar_wait(fullb, phF);
        if (st == 0) phF0 ^= 1; else if (st == 1) phF1 ^= 1; else phF2 ^= 1;

        const unsigned sA = sb + st * 32768;
        const unsigned sB = sA + 16384;

#pragma unroll
        for (int ks = 0; ks < 4; ks++) {
            const unsigned kb = (unsigned)(ks * 32 + lhi * 16);
            unsigned a0[4], a1[4];
            ldsm_x4(a0[0], a0[1], a0[2], a0[3],
                    sA + sw128((unsigned)((wr * 32 + l15) * 128) + kb));
            ldsm_x4(a1[0], a1[1], a1[2], a1[3],
                    sA + sw128((unsigned)((wr * 32 + 16 + l15) * 128) + kb));
            unsigned bf[4][4];
#pragma unroll
            for (int nb = 0; nb < 4; nb++)
                ldsm_x4(bf[nb][0], bf[nb][1], bf[nb][2], bf[nb][3],
                        sB + sw128((unsigned)((wc * 64 + nb * 16 + l15) * 128) + kb));
#pragma unroll
            for (int nb = 0; nb < 4; nb++) {
                mma16816(acc[0][2 * nb], a0[0], a0[1], a0[2], a0[3], bf[nb][0], bf[nb][2]);
                mma16816(acc[0][2 * nb + 1], a0[0], a0[1], a0[2], a0[3], bf[nb][1], bf[nb][3]);
                mma16816(acc[1][2 * nb], a1[0], a1[1], a1[2], a1[3], bf[nb][0], bf[nb][2]);
                mma16816(acc[1][2 * nb + 1], a1[0], a1[1], a1[2], a1[3], bf[nb][1], bf[nb][3]);
            }
        }

        MBAR_ARRIVE(emptyb);
        if (tid == 0 && k + NST < 16) {
            int phE = (st == 0) ? phE0 : (st == 1) ? phE1 : phE2;
            mbar_wait(emptyb, phE);
            if (st == 0) phE0 ^= 1; else if (st == 1) phE1 ^= 1; else phE2 ^= 1;
            MBAR_EXPECT(fullb, 32768);
            bulk_g2s(sA, gA + (size_t)(k + NST) * 16384, 16384, fullb);
            bulk_g2s(sB, gB0 + (size_t)(k + NST) * 131072, 16384, fullb);
        }
    }

    // ---------------- fused epilogue: score += sum_col tanh(d + c) * Wout ----------------
    const int lq = lane & 3, lr = lane >> 2;
    float p[2][2] = {{0.f, 0.f}, {0.f, 0.f}};
#pragma unroll
    for (int nf = 0; nf < 8; nf++) {
        const int col = nc * 128 + wc * 64 + nf * 8 + lq * 2;
        const float2 c01 = __ldg(reinterpret_cast<const float2*>(&g_cbias[b * 1024 + col]));
        const float2 w01 = __ldg(reinterpret_cast<const float2*>(&Wout[col]));
#pragma unroll
        for (int mf = 0; mf < 2; mf++)
#pragma unroll
            for (int h = 0; h < 2; h++) {
                p[mf][h] += tanh_fast(acc[mf][nf][h * 2 + 0] + c01.x) * w01.x +
                            tanh_fast(acc[mf][nf][h * 2 + 1] + c01.y) * w01.y;
            }
    }
#pragma unroll
    for (int mf = 0; mf < 2; mf++)
#pragma unroll
        for (int h = 0; h < 2; h++) {
            float v = p[mf][h];
            v += __shfl_xor_sync(0xFFFFFFFFu, v, 1);
            v += __shfl_xor_sync(0xFFFFFFFFu, v, 2);
            if (lq == 0)
                red_add(&g_scores[mt * 128 + wr * 32 + mf * 16 + h * 8 + lr], v);
        }
}

// ======================= kernel 3: fused softmax + context (reads fp16 tiles) =======================
__global__ void __launch_bounds__(256) ctx_kernel(float* __restrict__ out) {
    __shared__ float attn[2048];
    __shared__ float red[256];
    __shared__ float2 sred[8][32];
    const int b = blockIdx.x, kc = blockIdx.y;
    const int tid = threadIdx.x, w = tid >> 5, l = tid & 31;

    float v[8];
    float mx = -1e30f;
#pragma unroll
    for (int i = 0; i < 8; i++) {
        v[i] = g_scores[b * 2048 + tid + i * 256];
        mx = fmaxf(mx, v[i]);
    }
    red[tid] = mx;
    __syncthreads();
    for (int s = 128; s > 0; s >>= 1) {
        if (tid < s) red[tid] = fmaxf(red[tid], red[tid + s]);
        __syncthreads();
    }
    mx = red[0];
    __syncthreads();
    float sum = 0.f;
#pragma unroll
    for (int i = 0; i < 8; i++) {
        v[i] = __expf(v[i] - mx);
        sum += v[i];
        attn[tid + i * 256] = v[i];
    }
    red[tid] = sum;
    __syncthreads();
    for (int s = 128; s > 0; s >>= 1) {
        if (tid < s) red[tid] += red[tid + s];
        __syncthreads();
    }
    const float inv = 1.0f / red[0];
    __syncthreads();

    float ax = 0.f, ay = 0.f;
#pragma unroll 1
    for (int mtl = 0; mtl < 16; mtl++) {
        const unsigned char* tb = g_encb + (((size_t)(b * 16 + mtl)) * 16 + kc) * 16384;
#pragma unroll
        for (int r8 = 0; r8 < 16; r8++) {
            const int r = r8 * 8 + w;
            const unsigned off = sw128((unsigned)(r * 128 + 4 * l));
            const unsigned hv = *reinterpret_cast<const unsigned*>(tb + off);
            const __half2 h2 = *reinterpret_cast<const __half2*>(&hv);
            const float2 e = __half22float2(h2);
            const float a = attn[mtl * 128 + r];
            ax += a * e.x;
            ay += a * e.y;
        }
    }
    sred[w][l] = make_float2(ax, ay);
    __syncthreads();
    if (tid < 32) {
        float sx = 0.f, sy = 0.f;
#pragma unroll
        for (int ww = 0; ww < 8; ww++) {
            sx += sred[ww][tid].x;
            sy += sred[ww][tid].y;
        }
        out[b * 1024 + kc * 64 + 2 * tid]     = sx * inv;
        out[b * 1024 + kc * 64 + 2 * tid + 1] = sy * inv;
    }
}

// ======================= launch =======================
extern "C" void kernel_launch(void* const* d_in, const int* in_sizes, int n_in,
                              void* d_out, int out_size) {
    const float* enc  = (const float*)d_in[0];
    const float* dec  = (const float*)d_in[1];
    const float* Wk   = (const float*)d_in[2];
    const float* bk   = (const float*)d_in[3];
    const float* Wq   = (const float*)d_in[4];
    const float* bq   = (const float*)d_in[5];
    const float* Wout = (const float*)d_in[6];
    // d_in[7] = bout: constant shift, cancels in softmax. d_in[8] unused.
    float* out = (float*)d_out;

    static int cfg_done = 0;
    if (!cfg_done) {
        cudaFuncSetAttribute(gemm_score_kernel,
                             cudaFuncAttributeMaxDynamicSharedMemorySize, SMEM_GEMM);
        cfg_done = 1;
    }

    prep_kernel<<<4160, 256>>>(Wk, dec, Wq, bq, bk);
    gemm_score_kernel<<<4096, 256, SMEM_GEMM>>>(enc, Wout);
    ctx_kernel<<<dim3(32, 16), 256>>>(out);
}

// round 6
// speedup vs baseline: 1.4096x; 1.4096x over previous
#include <cuda_runtime.h>
#include <cuda_fp16.h>
#include <cstdint>
#include <cstddef>

#define DINL __device__ __forceinline__

// Problem: B=32, T=2048, H=1024
// inputs: 0 enc[32,2048,1024] f32, 1 dec[1,32,1024] f32, 2 Wk[1024,1024] f32,
//         3 bk[1024], 4 Wq[1024,1024], 5 bq[1024], 6 Wout[1024], 7 bout, 8 inputs(unused)
// out: [32,1,1024] f32

// ======================= static device scratch =======================
// enc fp16 tiles: [mt 0..511][kc 0..15] each 128 rows x 64 k-cols, SW128, 16 KB
__device__ __align__(1024) unsigned char g_encb[512ull * 16ull * 16384ull];  // 128 MB
// Wk fp16 tiles: [kc 0..15][ncB 0..7] each 128 n-rows x 64 k-cols, SW128, 16 KB
__device__ __align__(1024) unsigned char g_wkb[16ull * 8ull * 16384ull];     // 2 MB
__device__ float g_cbias[32 * 1024];
__device__ float g_scores[32 * 2048];

// ======================= PTX helpers =======================
DINL unsigned smem_u32(const void* p) {
    unsigned a;
    asm("{ .reg .u64 t; cvta.to.shared.u64 t, %1; cvt.u32.u64 %0, t; }" : "=r"(a) : "l"(p));
    return a;
}

#define MBAR_INIT(a, c) \
    asm volatile("mbarrier.init.shared.b64 [%0], %1;" :: "r"(a), "r"(c) : "memory")
#define MBAR_EXPECT(a, b) \
    asm volatile("mbarrier.arrive.expect_tx.shared.b64 _, [%0], %1;" :: "r"(a), "r"(b) : "memory")
#define MBAR_ARRIVE(a) \
    asm volatile("mbarrier.arrive.shared.b64 _, [%0];" :: "r"(a) : "memory")

DINL void mbar_wait(unsigned mbar, unsigned parity) {
    asm volatile(
        "{\n\t"
        ".reg .pred P;\n\t"
        "WL_%=:\n\t"
        "mbarrier.try_wait.parity.acquire.cta.shared::cta.b64 P, [%0], %1, 0x989680;\n\t"
        "@P bra.uni WD_%=;\n\t"
        "bra.uni WL_%=;\n\t"
        "WD_%=:\n\t"
        "}"
        :: "r"(mbar), "r"(parity) : "memory");
}

DINL void bulk_g2s(unsigned dst, const void* src, unsigned bytes, unsigned mbar) {
    asm volatile(
        "cp.async.bulk.shared::cluster.global.mbarrier::complete_tx::bytes [%0], [%1], %2, [%3];"
        :: "r"(dst), "l"(src), "r"(bytes), "r"(mbar) : "memory");
}

DINL void ldsm_x4(unsigned& r0, unsigned& r1, unsigned& r2, unsigned& r3, unsigned addr) {
    asm volatile("ldmatrix.sync.aligned.m8n8.x4.shared.b16 {%0,%1,%2,%3}, [%4];"
                 : "=r"(r0), "=r"(r1), "=r"(r2), "=r"(r3) : "r"(addr));
}

DINL void mma16816(float* d, unsigned a0, unsigned a1, unsigned a2, unsigned a3,
                   unsigned b0, unsigned b1) {
    asm volatile(
        "mma.sync.aligned.m16n8k16.row.col.f32.f16.f16.f32 "
        "{%0,%1,%2,%3},{%4,%5,%6,%7},{%8,%9},{%0,%1,%2,%3};"
        : "+f"(d[0]), "+f"(d[1]), "+f"(d[2]), "+f"(d[3])
        : "r"(a0), "r"(a1), "r"(a2), "r"(a3), "r"(b0), "r"(b1));
}

DINL float tanh_fast(float x) {
    float t;
    asm("tanh.approx.f32 %0, %1;" : "=f"(t) : "f"(x));
    return t;
}

DINL void red_add(float* p, float v) {
    asm volatile("red.global.add.f32 [%0], %1;" :: "l"(p), "f"(v) : "memory");
}

DINL unsigned sw128(unsigned off) { return off ^ ((off >> 3) & 0x70); }

DINL unsigned pkh2(float a, float b) {
    __half ha = __float2half_rn(a), hb = __float2half_rn(b);
    return ((unsigned)__half_as_ushort(hb) << 16) | (unsigned)__half_as_ushort(ha);
}

// ======================= kernel 1: enc f32 -> fp16 swizzled tiles =======================
__global__ void __launch_bounds__(256) conv_enc_kernel(const float* __restrict__ enc) {
    int mt = blockIdx.x >> 2;
    int rq = blockIdx.x & 3;                 // quarter: rows rq*32..rq*32+31
    const float* src = enc + ((size_t)mt * 128 + rq * 32) * 1024;
    unsigned char* dst = g_encb + (size_t)mt * 262144;
    for (int i = threadIdx.x; i < 32 * 128; i += 256) {   // (row within quarter) x col-block(8)
        int r = (i >> 7) + rq * 32;
        int col = (i & 127) * 8;
        float4 f0 = *reinterpret_cast<const float4*>(src + (size_t)(i >> 7) * 1024 + col);
        float4 f1 = *reinterpret_cast<const float4*>(src + (size_t)(i >> 7) * 1024 + col + 4);
        uint4 v = make_uint4(pkh2(f0.x, f0.y), pkh2(f0.z, f0.w),
                             pkh2(f1.x, f1.y), pkh2(f1.z, f1.w));
        int kc = col >> 6;
        int c = col & 63;
        unsigned off = sw128((unsigned)(r * 128 + c * 2));
        *reinterpret_cast<uint4*>(dst + (size_t)kc * 16384 + off) = v;
    }
}

// ======================= kernel 2: prep = conv_wk + zero scores + cbias =======================
// grid 4160: blocks 0..63 do Wk conversion + score zeroing; blocks 64..4159 do cbias.
__global__ void __launch_bounds__(256) prep_kernel(const float* __restrict__ Wk,
                                                   const float* __restrict__ dec,
                                                   const float* __restrict__ Wq,
                                                   const float* __restrict__ bq,
                                                   const float* __restrict__ bk) {
    const int bx = blockIdx.x, tid = threadIdx.x;
    if (bx < 64) {
        int zi = bx * 256 + tid;
        *reinterpret_cast<float4*>(g_scores + zi * 4) = make_float4(0.f, 0.f, 0.f, 0.f);

        for (int u = bx * 256 + tid; u < 1024 * 128; u += 64 * 256) {
            int h = u >> 7;
            int col = (u & 127) * 8;
            float4 f0 = *reinterpret_cast<const float4*>(Wk + (size_t)h * 1024 + col);
            float4 f1 = *reinterpret_cast<const float4*>(Wk + (size_t)h * 1024 + col + 4);
            uint4 v = make_uint4(pkh2(f0.x, f0.y), pkh2(f0.z, f0.w),
                                 pkh2(f1.x, f1.y), pkh2(f1.z, f1.w));
            int kc = col >> 6;
            int c = col & 63;
            int ncB = h >> 7;
            int nr = h & 127;
            unsigned off = sw128((unsigned)(nr * 128 + c * 2));
            *reinterpret_cast<uint4*>(g_wkb + ((size_t)kc * 8 + ncB) * 16384 + off) = v;
        }
    } else {
        int gw = (bx - 64) * 8 + (tid >> 5);
        int lane = tid & 31;
        int b = gw >> 10;
        int h = gw & 1023;
        float acc = 0.f;
#pragma unroll
        for (int it = 0; it < 8; it++) {
            int j = it * 128 + lane * 4;
            float4 d = *reinterpret_cast<const float4*>(dec + (size_t)b * 1024 + j);
            float4 w = *reinterpret_cast<const float4*>(Wq + (size_t)h * 1024 + j);
            acc += d.x * w.x + d.y * w.y + d.z * w.z + d.w * w.w;
        }
#pragma unroll
        for (int o = 16; o > 0; o >>= 1) acc += __shfl_down_sync(0xFFFFFFFFu, acc, o);
        if (lane == 0) g_cbias[b * 1024 + h] = acc + bq[h] + bk[h];
    }
}

// ======================= kernel 3: fp16 HMMA GEMM + fused tanh/Wout score =======================
// EXACT R3 mainloop (measured 325us): rolled k-loop, dynamic phases, per-thread empty arrives.
// CTA tile: M=128, N=128, K=1024. grid 4096: mt = bx>>3, nc = bx&7.
#define NST 3
#define SMEM_GEMM 98432
__global__ void __launch_bounds__(256, 2) gemm_score_kernel(const float* __restrict__ Wout) {
    extern __shared__ __align__(128) unsigned char smem[];
    const unsigned sb = smem_u32(smem);
    const unsigned OFF_FULL = 98304, OFF_EMPTY = 98336;

    const int tid = threadIdx.x, wid = tid >> 5, lane = tid & 31;
    const int wr = wid >> 1;          // warp row 0..3  -> rows wr*32..+32
    const int wc = wid & 1;           // warp col 0..1  -> cols wc*64..+64
    const int mt = blockIdx.x >> 3;
    const int nc = blockIdx.x & 7;
    const int b = mt >> 4;

    if (tid == 0) {
#pragma unroll
        for (int s = 0; s < NST; s++) {
            MBAR_INIT(sb + OFF_FULL + s * 8, 1);
            MBAR_INIT(sb + OFF_EMPTY + s * 8, 256);
        }
        asm volatile("fence.proxy.async.shared::cta;" ::: "memory");
    }
    __syncthreads();

    const unsigned char* gA = g_encb + (size_t)mt * 262144;        // + kc*16384
    const unsigned char* gB0 = g_wkb + (size_t)nc * 16384;         // + kc*8*16384

    // prologue: fill all stages
    if (tid == 0) {
#pragma unroll
        for (int s = 0; s < NST; s++) {
            MBAR_EXPECT(sb + OFF_FULL + s * 8, 32768);
            bulk_g2s(sb + s * 32768, gA + (size_t)s * 16384, 16384, sb + OFF_FULL + s * 8);
            bulk_g2s(sb + s * 32768 + 16384, gB0 + (size_t)s * 131072, 16384,
                     sb + OFF_FULL + s * 8);
        }
    }

    float acc[2][8][4];
#pragma unroll
    for (int mf = 0; mf < 2; mf++)
#pragma unroll
        for (int nf = 0; nf < 8; nf++)
#pragma unroll
            for (int e = 0; e < 4; e++) acc[mf][nf][e] = 0.f;

    int phF0 = 0, phF1 = 0, phF2 = 0, phE0 = 0, phE1 = 0, phE2 = 0;
    const int l15 = lane & 15;
    const int lhi = lane >> 4;

#pragma unroll 1
    for (int k = 0; k < 16; k++) {
        const int st = k % NST;
        const unsigned fullb = sb + OFF_FULL + st * 8;
        const unsigned emptyb = sb + OFF_EMPTY + st * 8;
        int phF = (st == 0) ? phF0 : (st == 1) ? phF1 : phF2;
        mbar_wait(fullb, phF);
        if (st == 0) phF0 ^= 1; else if (st == 1) phF1 ^= 1; else phF2 ^= 1;

        const unsigned sA = sb + st * 32768;
        const unsigned sB = sA + 16384;

#pragma unroll
        for (int ks = 0; ks < 4; ks++) {
            const unsigned kb = (unsigned)(ks * 32 + lhi * 16);
            unsigned a0[4], a1[4];
            ldsm_x4(a0[0], a0[1], a0[2], a0[3],
                    sA + sw128((unsigned)((wr * 32 + l15) * 128) + kb));
            ldsm_x4(a1[0], a1[1], a1[2], a1[3],
                    sA + sw128((unsigned)((wr * 32 + 16 + l15) * 128) + kb));
            unsigned bf[4][4];
#pragma unroll
            for (int nb = 0; nb < 4; nb++)
                ldsm_x4(bf[nb][0], bf[nb][1], bf[nb][2], bf[nb][3],
                        sB + sw128((unsigned)((wc * 64 + nb * 16 + l15) * 128) + kb));
#pragma unroll
            for (int nb = 0; nb < 4; nb++) {
                mma16816(acc[0][2 * nb], a0[0], a0[1], a0[2], a0[3], bf[nb][0], bf[nb][2]);
                mma16816(acc[0][2 * nb + 1], a0[0], a0[1], a0[2], a0[3], bf[nb][1], bf[nb][3]);
                mma16816(acc[1][2 * nb], a1[0], a1[1], a1[2], a1[3], bf[nb][0], bf[nb][2]);
                mma16816(acc[1][2 * nb + 1], a1[0], a1[1], a1[2], a1[3], bf[nb][1], bf[nb][3]);
            }
        }

        MBAR_ARRIVE(emptyb);
        if (tid == 0 && k + NST < 16) {
            int phE = (st == 0) ? phE0 : (st == 1) ? phE1 : phE2;
            mbar_wait(emptyb, phE);
            if (st == 0) phE0 ^= 1; else if (st == 1) phE1 ^= 1; else phE2 ^= 1;
            MBAR_EXPECT(fullb, 32768);
            bulk_g2s(sA, gA + (size_t)(k + NST) * 16384, 16384, fullb);
            bulk_g2s(sB, gB0 + (size_t)(k + NST) * 131072, 16384, fullb);
        }
    }

    // ---------------- fused epilogue: score += sum_col tanh(d + c) * Wout ----------------
    const int lq = lane & 3, lr = lane >> 2;
    float p[2][2] = {{0.f, 0.f}, {0.f, 0.f}};
#pragma unroll
    for (int nf = 0; nf < 8; nf++) {
        const int col = nc * 128 + wc * 64 + nf * 8 + lq * 2;
        const float2 c01 = __ldg(reinterpret_cast<const float2*>(&g_cbias[b * 1024 + col]));
        const float2 w01 = __ldg(reinterpret_cast<const float2*>(&Wout[col]));
#pragma unroll
        for (int mf = 0; mf < 2; mf++)
#pragma unroll
            for (int h = 0; h < 2; h++) {
                p[mf][h] += tanh_fast(acc[mf][nf][h * 2 + 0] + c01.x) * w01.x +
                            tanh_fast(acc[mf][nf][h * 2 + 1] + c01.y) * w01.y;
            }
    }
#pragma unroll
    for (int mf = 0; mf < 2; mf++)
#pragma unroll
        for (int h = 0; h < 2; h++) {
            float v = p[mf][h];
            v += __shfl_xor_sync(0xFFFFFFFFu, v, 1);
            v += __shfl_xor_sync(0xFFFFFFFFu, v, 2);
            if (lq == 0)
                red_add(&g_scores[mt * 128 + wr * 32 + mf * 16 + h * 8 + lr], v);
        }
}

// ======================= kernel 4: fused softmax + context (reads fp16 tiles) =======================
__global__ void __launch_bounds__(256) ctx_kernel(float* __restrict__ out) {
    __shared__ float attn[2048];
    __shared__ float red[256];
    __shared__ float2 sred[8][32];
    const int b = blockIdx.x, kc = blockIdx.y;
    const int tid = threadIdx.x, w = tid >> 5, l = tid & 31;

    float v[8];
    float mx = -1e30f;
#pragma unroll
    for (int i = 0; i < 8; i++) {
        v[i] = g_scores[b * 2048 + tid + i * 256];
        mx = fmaxf(mx, v[i]);
    }
    red[tid] = mx;
    __syncthreads();
    for (int s = 128; s > 0; s >>= 1) {
        if (tid < s) red[tid] = fmaxf(red[tid], red[tid + s]);
        __syncthreads();
    }
    mx = red[0];
    __syncthreads();
    float sum = 0.f;
#pragma unroll
    for (int i = 0; i < 8; i++) {
        v[i] = __expf(v[i] - mx);
        sum += v[i];
        attn[tid + i * 256] = v[i];
    }
    red[tid] = sum;
    __syncthreads();
    for (int s = 128; s > 0; s >>= 1) {
        if (tid < s) red[tid] += red[tid + s];
        __syncthreads();
    }
    const float inv = 1.0f / red[0];
    __syncthreads();

    float ax = 0.f, ay = 0.f;
#pragma unroll 1
    for (int mtl = 0; mtl < 16; mtl++) {
        const unsigned char* tb = g_encb + (((size_t)(b * 16 + mtl)) * 16 + kc) * 16384;
#pragma unroll
        for (int r8 = 0; r8 < 16; r8++) {
            const int r = r8 * 8 + w;
            const unsigned off = sw128((unsigned)(r * 128 + 4 * l));
            const unsigned hv = *reinterpret_cast<const unsigned*>(tb + off);
            const __half2 h2 = *reinterpret_cast<const __half2*>(&hv);
            const float2 e = __half22float2(h2);
            const float a = attn[mtl * 128 + r];
            ax += a * e.x;
            ay += a * e.y;
        }
    }
    sred[w][l] = make_float2(ax, ay);
    __syncthreads();
    if (tid < 32) {
        float sx = 0.f, sy = 0.f;
#pragma unroll
        for (int ww = 0; ww < 8; ww++) {
            sx += sred[ww][tid].x;
            sy += sred[ww][tid].y;
        }
        out[b * 1024 + kc * 64 + 2 * tid]     = sx * inv;
        out[b * 1024 + kc * 64 + 2 * tid + 1] = sy * inv;
    }
}

// ======================= launch =======================
extern "C" void kernel_launch(void* const* d_in, const int* in_sizes, int n_in,
                              void* d_out, int out_size) {
    const float* enc  = (const float*)d_in[0];
    const float* dec  = (const float*)d_in[1];
    const float* Wk   = (const float*)d_in[2];
    const float* bk   = (const float*)d_in[3];
    const float* Wq   = (const float*)d_in[4];
    const float* bq   = (const float*)d_in[5];
    const float* Wout = (const float*)d_in[6];
    // d_in[7] = bout: constant shift, cancels in softmax. d_in[8] unused.
    float* out = (float*)d_out;

    static int cfg_done = 0;
    if (!cfg_done) {
        cudaFuncSetAttribute(gemm_score_kernel,
                             cudaFuncAttributeMaxDynamicSharedMemorySize, SMEM_GEMM);
        cfg_done = 1;
    }

    conv_enc_kernel<<<2048, 256>>>(enc);
    prep_kernel<<<4160, 256>>>(Wk, dec, Wq, bq, bk);
    gemm_score_kernel<<<4096, 256, SMEM_GEMM>>>(Wout);
    ctx_kernel<<<dim3(32, 16), 256>>>(out);
}

// round 8
// speedup vs baseline: 1.7262x; 1.2246x over previous
#include <cuda_runtime.h>
#include <cuda_fp16.h>
#include <cstdint>
#include <cstddef>

#define DINL __device__ __forceinline__

// Problem: B=32, T=2048, H=1024
// inputs: 0 enc[32,2048,1024] f32, 1 dec[1,32,1024] f32, 2 Wk[1024,1024] f32,
//         3 bk[1024], 4 Wq[1024,1024], 5 bq[1024], 6 Wout[1024], 7 bout, 8 inputs(unused)
// out: [32,1,1024] f32

// ======================= static device scratch =======================
// enc fp16 tiles: [mt 0..511][kc 0..15] each 128 rows x 64 k-cols, SW128, 16 KB
__device__ __align__(1024) unsigned char g_encb[512ull * 16ull * 16384ull];  // 128 MB
// Wk fp16 tiles: [kc 0..15][ncB 0..7] each 128 n-rows x 64 k-cols, SW128, 16 KB
__device__ __align__(1024) unsigned char g_wkb[16ull * 8ull * 16384ull];     // 2 MB
__device__ float g_cbias[32 * 1024];
__device__ float g_scores[32 * 2048];
__device__ float g_ctxpart[4 * 32 * 1024];

// ======================= PTX helpers =======================
DINL unsigned smem_u32(const void* p) {
    unsigned a;
    asm("{ .reg .u64 t; cvta.to.shared.u64 t, %1; cvt.u32.u64 %0, t; }" : "=r"(a) : "l"(p));
    return a;
}

#define MBAR_INIT(a, c) \
    asm volatile("mbarrier.init.shared.b64 [%0], %1;" :: "r"(a), "r"(c) : "memory")
#define MBAR_EXPECT(a, b) \
    asm volatile("mbarrier.arrive.expect_tx.shared.b64 _, [%0], %1;" :: "r"(a), "r"(b) : "memory")
#define MBAR_ARRIVE(a) \
    asm volatile("mbarrier.arrive.shared.b64 _, [%0];" :: "r"(a) : "memory")

DINL void mbar_wait(unsigned mbar, unsigned parity) {
    asm volatile(
        "{\n\t"
        ".reg .pred P;\n\t"
        "WL_%=:\n\t"
        "mbarrier.try_wait.parity.acquire.cta.shared::cta.b64 P, [%0], %1, 0x989680;\n\t"
        "@P bra.uni WD_%=;\n\t"
        "bra.uni WL_%=;\n\t"
        "WD_%=:\n\t"
        "}"
        :: "r"(mbar), "r"(parity) : "memory");
}

DINL void bulk_g2s(unsigned dst, const void* src, unsigned bytes, unsigned mbar) {
    asm volatile(
        "cp.async.bulk.shared::cluster.global.mbarrier::complete_tx::bytes [%0], [%1], %2, [%3];"
        :: "r"(dst), "l"(src), "r"(bytes), "r"(mbar) : "memory");
}

DINL void ldsm_x4(unsigned& r0, unsigned& r1, unsigned& r2, unsigned& r3, unsigned addr) {
    asm volatile("ldmatrix.sync.aligned.m8n8.x4.shared.b16 {%0,%1,%2,%3}, [%4];"
                 : "=r"(r0), "=r"(r1), "=r"(r2), "=r"(r3) : "r"(addr));
}

DINL void mma16816(float* d, unsigned a0, unsigned a1, unsigned a2, unsigned a3,
                   unsigned b0, unsigned b1) {
    asm volatile(
        "mma.sync.aligned.m16n8k16.row.col.f32.f16.f16.f32 "
        "{%0,%1,%2,%3},{%4,%5,%6,%7},{%8,%9},{%0,%1,%2,%3};"
        : "+f"(d[0]), "+f"(d[1]), "+f"(d[2]), "+f"(d[3])
        : "r"(a0), "r"(a1), "r"(a2), "r"(a3), "r"(b0), "r"(b1));
}

DINL float tanh_fast(float x) {
    float t;
    asm("tanh.approx.f32 %0, %1;" : "=f"(t) : "f"(x));
    return t;
}

DINL void red_add(float* p, float v) {
    asm volatile("red.global.add.f32 [%0], %1;" :: "l"(p), "f"(v) : "memory");
}

DINL unsigned sw128(unsigned off) { return off ^ ((off >> 3) & 0x70); }

DINL unsigned pkh2(float a, float b) {
    __half ha = __float2half_rn(a), hb = __float2half_rn(b);
    return ((unsigned)__half_as_ushort(hb) << 16) | (unsigned)__half_as_ushort(ha);
}

// ======================= kernel 1: merged prep =======================
// grid 6208: [0,2048) enc conversion; [2048,2112) Wk conversion + score zeroing;
//            [2112,6208) cbias (8 warps per block).
__global__ void __launch_bounds__(256) prep_kernel(const float* __restrict__ enc,
                                                   const float* __restrict__ Wk,
                                                   const float* __restrict__ dec,
                                                   const float* __restrict__ Wq,
                                                   const float* __restrict__ bq,
                                                   const float* __restrict__ bk) {
    const int bx = blockIdx.x, tid = threadIdx.x;
    if (bx < 2048) {
        // enc f32 -> fp16 swizzled tiles
        int mt = bx >> 2;
        int rq = bx & 3;                 // quarter: rows rq*32..rq*32+31
        const float* src = enc + ((size_t)mt * 128 + rq * 32) * 1024;
        unsigned char* dst = g_encb + (size_t)mt * 262144;
        for (int i = tid; i < 32 * 128; i += 256) {
            int r = (i >> 7) + rq * 32;
            int col = (i & 127) * 8;
            float4 f0 = *reinterpret_cast<const float4*>(src + (size_t)(i >> 7) * 1024 + col);
            float4 f1 = *reinterpret_cast<const float4*>(src + (size_t)(i >> 7) * 1024 + col + 4);
            uint4 v = make_uint4(pkh2(f0.x, f0.y), pkh2(f0.z, f0.w),
                                 pkh2(f1.x, f1.y), pkh2(f1.z, f1.w));
            int kc = col >> 6;
            int c = col & 63;
            unsigned off = sw128((unsigned)(r * 128 + c * 2));
            *reinterpret_cast<uint4*>(dst + (size_t)kc * 16384 + off) = v;
        }
    } else if (bx < 2112) {
        const int zb = bx - 2048;
        int zi = zb * 256 + tid;
        *reinterpret_cast<float4*>(g_scores + zi * 4) = make_float4(0.f, 0.f, 0.f, 0.f);

        for (int u = zb * 256 + tid; u < 1024 * 128; u += 64 * 256) {
            int h = u >> 7;
            int col = (u & 127) * 8;
            float4 f0 = *reinterpret_cast<const float4*>(Wk + (size_t)h * 1024 + col);
            float4 f1 = *reinterpret_cast<const float4*>(Wk + (size_t)h * 1024 + col + 4);
            uint4 v = make_uint4(pkh2(f0.x, f0.y), pkh2(f0.z, f0.w),
                                 pkh2(f1.x, f1.y), pkh2(f1.z, f1.w));
            int kc = col >> 6;
            int c = col & 63;
            int ncB = h >> 7;
            int nr = h & 127;
            unsigned off = sw128((unsigned)(nr * 128 + c * 2));
            *reinterpret_cast<uint4*>(g_wkb + ((size_t)kc * 8 + ncB) * 16384 + off) = v;
        }
    } else {
        int gw = (bx - 2112) * 8 + (tid >> 5);
        int lane = tid & 31;
        int b = gw >> 10;
        int h = gw & 1023;
        float acc = 0.f;
#pragma unroll
        for (int it = 0; it < 8; it++) {
            int j = it * 128 + lane * 4;
            float4 d = *reinterpret_cast<const float4*>(dec + (size_t)b * 1024 + j);
            float4 w = *reinterpret_cast<const float4*>(Wq + (size_t)h * 1024 + j);
            acc += d.x * w.x + d.y * w.y + d.z * w.z + d.w * w.w;
        }
#pragma unroll
        for (int o = 16; o > 0; o >>= 1) acc += __shfl_down_sync(0xFFFFFFFFu, acc, o);
        if (lane == 0) g_cbias[b * 1024 + h] = acc + bq[h] + bk[h];
    }
}

// ======================= kernel 2: fp16 HMMA GEMM + fused tanh/Wout score =======================
// UNCHANGED measured-good R3 mainloop. CTA tile M=128,N=128,K=1024. grid 4096.
#define NST 3
#define SMEM_GEMM 98432
__global__ void __launch_bounds__(256, 2) gemm_score_kernel(const float* __restrict__ Wout) {
    extern __shared__ __align__(128) unsigned char smem[];
    const unsigned sb = smem_u32(smem);
    const unsigned OFF_FULL = 98304, OFF_EMPTY = 98336;

    const int tid = threadIdx.x, wid = tid >> 5, lane = tid & 31;
    const int wr = wid >> 1;
    const int wc = wid & 1;
    const int mt = blockIdx.x >> 3;
    const int nc = blockIdx.x & 7;
    const int b = mt >> 4;

    if (tid == 0) {
#pragma unroll
        for (int s = 0; s < NST; s++) {
            MBAR_INIT(sb + OFF_FULL + s * 8, 1);
            MBAR_INIT(sb + OFF_EMPTY + s * 8, 256);
        }
        asm volatile("fence.proxy.async.shared::cta;" ::: "memory");
    }
    __syncthreads();

    const unsigned char* gA = g_encb + (size_t)mt * 262144;
    const unsigned char* gB0 = g_wkb + (size_t)nc * 16384;

    if (tid == 0) {
#pragma unroll
        for (int s = 0; s < NST; s++) {
            MBAR_EXPECT(sb + OFF_FULL + s * 8, 32768);
            bulk_g2s(sb + s * 32768, gA + (size_t)s * 16384, 16384, sb + OFF_FULL + s * 8);
            bulk_g2s(sb + s * 32768 + 16384, gB0 + (size_t)s * 131072, 16384,
                     sb + OFF_FULL + s * 8);
        }
    }

    float acc[2][8][4];
#pragma unroll
    for (int mf = 0; mf < 2; mf++)
#pragma unroll
        for (int nf = 0; nf < 8; nf++)
#pragma unroll
            for (int e = 0; e < 4; e++) acc[mf][nf][e] = 0.f;

    int phF0 = 0, phF1 = 0, phF2 = 0, phE0 = 0, phE1 = 0, phE2 = 0;
    const int l15 = lane & 15;
    const int lhi = lane >> 4;

#pragma unroll 1
    for (int k = 0; k < 16; k++) {
        const int st = k % NST;
        const unsigned fullb = sb + OFF_FULL + st * 8;
        const unsigned emptyb = sb + OFF_EMPTY + st * 8;
        int phF = (st == 0) ? phF0 : (st == 1) ? phF1 : phF2;
        mbar_wait(fullb, phF);
        if (st == 0) phF0 ^= 1; else if (st == 1) phF1 ^= 1; else phF2 ^= 1;

        const unsigned sA = sb + st * 32768;
        const unsigned sB = sA + 16384;

#pragma unroll
        for (int ks = 0; ks < 4; ks++) {
            const unsigned kb = (unsigned)(ks * 32 + lhi * 16);
            unsigned a0[4], a1[4];
            ldsm_x4(a0[0], a0[1], a0[2], a0[3],
                    sA + sw128((unsigned)((wr * 32 + l15) * 128) + kb));
            ldsm_x4(a1[0], a1[1], a1[2], a1[3],
                    sA + sw128((unsigned)((wr * 32 + 16 + l15) * 128) + kb));
            unsigned bf[4][4];
#pragma unroll
            for (int nb = 0; nb < 4; nb++)
                ldsm_x4(bf[nb][0], bf[nb][1], bf[nb][2], bf[nb][3],
                        sB + sw128((unsigned)((wc * 64 + nb * 16 + l15) * 128) + kb));
#pragma unroll
            for (int nb = 0; nb < 4; nb++) {
                mma16816(acc[0][2 * nb], a0[0], a0[1], a0[2], a0[3], bf[nb][0], bf[nb][2]);
                mma16816(acc[0][2 * nb + 1], a0[0], a0[1], a0[2], a0[3], bf[nb][1], bf[nb][3]);
                mma16816(acc[1][2 * nb], a1[0], a1[1], a1[2], a1[3], bf[nb][0], bf[nb][2]);
                mma16816(acc[1][2 * nb + 1], a1[0], a1[1], a1[2], a1[3], bf[nb][1], bf[nb][3]);
            }
        }

        MBAR_ARRIVE(emptyb);
        if (tid == 0 && k + NST < 16) {
            int phE = (st == 0) ? phE0 : (st == 1) ? phE1 : phE2;
            mbar_wait(emptyb, phE);
            if (st == 0) phE0 ^= 1; else if (st == 1) phE1 ^= 1; else phE2 ^= 1;
            MBAR_EXPECT(fullb, 32768);
            bulk_g2s(sA, gA + (size_t)(k + NST) * 16384, 16384, fullb);
            bulk_g2s(sB, gB0 + (size_t)(k + NST) * 131072, 16384, fullb);
        }
    }

    const int lq = lane & 3, lr = lane >> 2;
    float p[2][2] = {{0.f, 0.f}, {0.f, 0.f}};
#pragma unroll
    for (int nf = 0; nf < 8; nf++) {
        const int col = nc * 128 + wc * 64 + nf * 8 + lq * 2;
        const float2 c01 = __ldg(reinterpret_cast<const float2*>(&g_cbias[b * 1024 + col]));
        const float2 w01 = __ldg(reinterpret_cast<const float2*>(&Wout[col]));
#pragma unroll
        for (int mf = 0; mf < 2; mf++)
#pragma unroll
            for (int h = 0; h < 2; h++) {
                p[mf][h] += tanh_fast(acc[mf][nf][h * 2 + 0] + c01.x) * w01.x +
                            tanh_fast(acc[mf][nf][h * 2 + 1] + c01.y) * w01.y;
            }
    }
#pragma unroll
    for (int mf = 0; mf < 2; mf++)
#pragma unroll
        for (int h = 0; h < 2; h++) {
            float v = p[mf][h];
            v += __shfl_xor_sync(0xFFFFFFFFu, v, 1);
            v += __shfl_xor_sync(0xFFFFFFFFu, v, 2);
            if (lq == 0)
                red_add(&g_scores[mt * 128 + wr * 32 + mf * 16 + h * 8 + lr], v);
        }
}

// ======================= kernel 3: softmax over T=2048 per batch (in place) =======================
__global__ void __launch_bounds__(256) softmax_kernel() {
    __shared__ float red[256];
    int b = blockIdx.x, tid = threadIdx.x;
    float v[8];
    float mx = -1e30f;
#pragma unroll
    for (int i = 0; i < 8; i++) {
        v[i] = g_scores[b * 2048 + tid + i * 256];
        mx = fmaxf(mx, v[i]);
    }
    red[tid] = mx;
    __syncthreads();
    for (int s = 128; s > 0; s >>= 1) {
        if (tid < s) red[tid] = fmaxf(red[tid], red[tid + s]);
        __syncthreads();
    }
    mx = red[0];
    __syncthreads();
    float sum = 0.f;
#pragma unroll
    for (int i = 0; i < 8; i++) {
        v[i] = __expf(v[i] - mx);
        sum += v[i];
    }
    red[tid] = sum;
    __syncthreads();
    for (int s = 128; s > 0; s >>= 1) {
        if (tid < s) red[tid] += red[tid + s];
        __syncthreads();
    }
    float inv = 1.0f / red[0];
#pragma unroll
    for (int i = 0; i < 8; i++) g_scores[b * 2048 + tid + i * 256] = v[i] * inv;
}

// ======================= kernel 4: context partials (uint4 loads, 2048 CTAs) =======================
// grid (32 b, 16 kc, 4 ts): each block handles 4 M-tiles (512 tokens) x 64 h values.
// Warp reads 4 rows per uint4 load: lane l -> row (l>>3), 16B chunk (l&7) within the 128B row.
__global__ void __launch_bounds__(256) ctx_kernel() {
    __shared__ float attn_s[512];
    __shared__ float sacc[8][64];
    const int b = blockIdx.x, kc = blockIdx.y, ts = blockIdx.z;
    const int tid = threadIdx.x, w = tid >> 5, l = tid & 31;
    const int lo = l & 7, lr = l >> 3;

    if (tid < 128)
        reinterpret_cast<float4*>(attn_s)[tid] =
            reinterpret_cast<const float4*>(g_scores + b * 2048 + ts * 512)[tid];
    __syncthreads();

    float acc[8];
#pragma unroll
    for (int j = 0; j < 8; j++) acc[j] = 0.f;

#pragma unroll
    for (int i = 0; i < 4; i++) {
        const unsigned char* tb =
            g_encb + (((size_t)(b * 16 + ts * 4 + i)) * 16 + kc) * 16384;
#pragma unroll
        for (int rc = 0; rc < 4; rc++) {
            const int r = rc * 32 + w * 4 + lr;
            const unsigned off = sw128((unsigned)(r * 128 + lo * 16));
            const uint4 v = *reinterpret_cast<const uint4*>(tb + off);
            const float a = attn_s[i * 128 + r];
            const float2 e0 = __half22float2(*reinterpret_cast<const __half2*>(&v.x));
            const float2 e1 = __half22float2(*reinterpret_cast<const __half2*>(&v.y));
            const float2 e2 = __half22float2(*reinterpret_cast<const __half2*>(&v.z));
            const float2 e3 = __half22float2(*reinterpret_cast<const __half2*>(&v.w));
            acc[0] += a * e0.x; acc[1] += a * e0.y;
            acc[2] += a * e1.x; acc[3] += a * e1.y;
            acc[4] += a * e2.x; acc[5] += a * e2.y;
            acc[6] += a * e3.x; acc[7] += a * e3.y;
        }
    }

    // reduce across lanes with same lo (rows): xor 8, 16
#pragma unroll
    for (int j = 0; j < 8; j++) {
        acc[j] += __shfl_xor_sync(0xFFFFFFFFu, acc[j], 8);
        acc[j] += __shfl_xor_sync(0xFFFFFFFFu, acc[j], 16);
    }
    if (l < 8) {
#pragma unroll
        for (int j = 0; j < 8; j++) sacc[w][lo * 8 + j] = acc[j];
    }
    __syncthreads();
    if (tid < 64) {
        float s = 0.f;
#pragma unroll
        for (int ww = 0; ww < 8; ww++) s += sacc[ww][tid];
        g_ctxpart[((size_t)ts * 32 + b) * 1024 + kc * 64 + tid] = s;
    }
}

// ======================= kernel 5: final add of 4 ts-partials =======================
__global__ void __launch_bounds__(256) final_kernel(float* __restrict__ out) {
    int b = blockIdx.x;
    for (int h = threadIdx.x; h < 1024; h += 256) {
        float s = 0.f;
#pragma unroll
        for (int ts = 0; ts < 4; ts++) s += g_ctxpart[((size_t)ts * 32 + b) * 1024 + h];
        out[b * 1024 + h] = s;
    }
}

// ======================= launch =======================
extern "C" void kernel_launch(void* const* d_in, const int* in_sizes, int n_in,
                              void* d_out, int out_size) {
    const float* enc  = (const float*)d_in[0];
    const float* dec  = (const float*)d_in[1];
    const float* Wk   = (const float*)d_in[2];
    const float* bk   = (const float*)d_in[3];
    const float* Wq   = (const float*)d_in[4];
    const float* bq   = (const float*)d_in[5];
    const float* Wout = (const float*)d_in[6];
    // d_in[7] = bout: constant shift, cancels in softmax. d_in[8] unused.
    float* out = (float*)d_out;

    static int cfg_done = 0;
    if (!cfg_done) {
        cudaFuncSetAttribute(gemm_score_kernel,
                             cudaFuncAttributeMaxDynamicSharedMemorySize, SMEM_GEMM);
        cfg_done = 1;
    }

    prep_kernel<<<6208, 256>>>(enc, Wk, dec, Wq, bq, bk);
    gemm_score_kernel<<<4096, 256, SMEM_GEMM>>>(Wout);
    softmax_kernel<<<32, 256>>>();
    ctx_kernel<<<dim3(32, 16, 4), 256>>>();
    final_kernel<<<32, 256>>>(out);
}

// round 9
// speedup vs baseline: 1.7510x; 1.0144x over previous
#include <cuda_runtime.h>
#include <cuda_fp16.h>
#include <cstdint>
#include <cstddef>

#define DINL __device__ __forceinline__

// Problem: B=32, T=2048, H=1024
// inputs: 0 enc[32,2048,1024] f32, 1 dec[1,32,1024] f32, 2 Wk[1024,1024] f32,
//         3 bk[1024], 4 Wq[1024,1024], 5 bq[1024], 6 Wout[1024], 7 bout, 8 inputs(unused)
// out: [32,1,1024] f32

// ======================= static device scratch =======================
// enc fp16 tiles: [mt 0..511][kc 0..15] each 128 rows x 64 k-cols, SW128, 16 KB
__device__ __align__(1024) unsigned char g_encb[512ull * 16ull * 16384ull];  // 128 MB
// Wk fp16 tiles: [kc 0..15][ncB 0..7] each 128 n-rows x 64 k-cols, SW128, 16 KB
__device__ __align__(1024) unsigned char g_wkb[16ull * 8ull * 16384ull];     // 2 MB
__device__ float g_cbias[32 * 1024];
__device__ float g_scores[32 * 2048];

// ======================= PTX helpers =======================
DINL unsigned smem_u32(const void* p) {
    unsigned a;
    asm("{ .reg .u64 t; cvta.to.shared.u64 t, %1; cvt.u32.u64 %0, t; }" : "=r"(a) : "l"(p));
    return a;
}

#define MBAR_INIT(a, c) \
    asm volatile("mbarrier.init.shared.b64 [%0], %1;" :: "r"(a), "r"(c) : "memory")
#define MBAR_EXPECT(a, b) \
    asm volatile("mbarrier.arrive.expect_tx.shared.b64 _, [%0], %1;" :: "r"(a), "r"(b) : "memory")
#define MBAR_ARRIVE(a) \
    asm volatile("mbarrier.arrive.shared.b64 _, [%0];" :: "r"(a) : "memory")

DINL void mbar_wait(unsigned mbar, unsigned parity) {
    asm volatile(
        "{\n\t"
        ".reg .pred P;\n\t"
        "WL_%=:\n\t"
        "mbarrier.try_wait.parity.acquire.cta.shared::cta.b64 P, [%0], %1, 0x989680;\n\t"
        "@P bra.uni WD_%=;\n\t"
        "bra.uni WL_%=;\n\t"
        "WD_%=:\n\t"
        "}"
        :: "r"(mbar), "r"(parity) : "memory");
}

DINL void bulk_g2s(unsigned dst, const void* src, unsigned bytes, unsigned mbar) {
    asm volatile(
        "cp.async.bulk.shared::cluster.global.mbarrier::complete_tx::bytes [%0], [%1], %2, [%3];"
        :: "r"(dst), "l"(src), "r"(bytes), "r"(mbar) : "memory");
}

DINL void ldsm_x4(unsigned& r0, unsigned& r1, unsigned& r2, unsigned& r3, unsigned addr) {
    asm volatile("ldmatrix.sync.aligned.m8n8.x4.shared.b16 {%0,%1,%2,%3}, [%4];"
                 : "=r"(r0), "=r"(r1), "=r"(r2), "=r"(r3) : "r"(addr));
}

DINL void mma16816(float* d, unsigned a0, unsigned a1, unsigned a2, unsigned a3,
                   unsigned b0, unsigned b1) {
    asm volatile(
        "mma.sync.aligned.m16n8k16.row.col.f32.f16.f16.f32 "
        "{%0,%1,%2,%3},{%4,%5,%6,%7},{%8,%9},{%0,%1,%2,%3};"
        : "+f"(d[0]), "+f"(d[1]), "+f"(d[2]), "+f"(d[3])
        : "r"(a0), "r"(a1), "r"(a2), "r"(a3), "r"(b0), "r"(b1));
}

DINL float tanh_fast(float x) {
    float t;
    asm("tanh.approx.f32 %0, %1;" : "=f"(t) : "f"(x));
    return t;
}

DINL void red_add(float* p, float v) {
    asm volatile("red.global.add.f32 [%0], %1;" :: "l"(p), "f"(v) : "memory");
}

DINL unsigned sw128(unsigned off) { return off ^ ((off >> 3) & 0x70); }

DINL unsigned pkh2(float a, float b) {
    __half ha = __float2half_rn(a), hb = __float2half_rn(b);
    return ((unsigned)__half_as_ushort(hb) << 16) | (unsigned)__half_as_ushort(ha);
}

// ======================= kernel 1: merged prep =======================
// grid 6208: [0,2048) enc conversion; [2048,2112) Wk conversion + zero scores/out;
//            [2112,6208) cbias (8 warps per block).
__global__ void __launch_bounds__(256) prep_kernel(const float* __restrict__ enc,
                                                   const float* __restrict__ Wk,
                                                   const float* __restrict__ dec,
                                                   const float* __restrict__ Wq,
                                                   const float* __restrict__ bq,
                                                   const float* __restrict__ bk,
                                                   float* __restrict__ out) {
    const int bx = blockIdx.x, tid = threadIdx.x;
    if (bx < 2048) {
        // enc f32 -> fp16 swizzled tiles
        int mt = bx >> 2;
        int rq = bx & 3;                 // quarter: rows rq*32..rq*32+31
        const float* src = enc + ((size_t)mt * 128 + rq * 32) * 1024;
        unsigned char* dst = g_encb + (size_t)mt * 262144;
        for (int i = tid; i < 32 * 128; i += 256) {
            int r = (i >> 7) + rq * 32;
            int col = (i & 127) * 8;
            float4 f0 = *reinterpret_cast<const float4*>(src + (size_t)(i >> 7) * 1024 + col);
            float4 f1 = *reinterpret_cast<const float4*>(src + (size_t)(i >> 7) * 1024 + col + 4);
            uint4 v = make_uint4(pkh2(f0.x, f0.y), pkh2(f0.z, f0.w),
                                 pkh2(f1.x, f1.y), pkh2(f1.z, f1.w));
            int kc = col >> 6;
            int c = col & 63;
            unsigned off = sw128((unsigned)(r * 128 + c * 2));
            *reinterpret_cast<uint4*>(dst + (size_t)kc * 16384 + off) = v;
        }
    } else if (bx < 2112) {
        const int zb = bx - 2048;
        int zi = zb * 256 + tid;
        *reinterpret_cast<float4*>(g_scores + zi * 4) = make_float4(0.f, 0.f, 0.f, 0.f);
        // zero out (32768 floats): 64 blocks x 256 threads x 2 floats
        *reinterpret_cast<float2*>(out + (size_t)zi * 2) = make_float2(0.f, 0.f);

        for (int u = zb * 256 + tid; u < 1024 * 128; u += 64 * 256) {
            int h = u >> 7;
            int col = (u & 127) * 8;
            float4 f0 = *reinterpret_cast<const float4*>(Wk + (size_t)h * 1024 + col);
            float4 f1 = *reinterpret_cast<const float4*>(Wk + (size_t)h * 1024 + col + 4);
            uint4 v = make_uint4(pkh2(f0.x, f0.y), pkh2(f0.z, f0.w),
                                 pkh2(f1.x, f1.y), pkh2(f1.z, f1.w));
            int kc = col >> 6;
            int c = col & 63;
            int ncB = h >> 7;
            int nr = h & 127;
            unsigned off = sw128((unsigned)(nr * 128 + c * 2));
            *reinterpret_cast<uint4*>(g_wkb + ((size_t)kc * 8 + ncB) * 16384 + off) = v;
        }
    } else {
        int gw = (bx - 2112) * 8 + (tid >> 5);
        int lane = tid & 31;
        int b = gw >> 10;
        int h = gw & 1023;
        float acc = 0.f;
#pragma unroll
        for (int it = 0; it < 8; it++) {
            int j = it * 128 + lane * 4;
            float4 d = *reinterpret_cast<const float4*>(dec + (size_t)b * 1024 + j);
            float4 w = *reinterpret_cast<const float4*>(Wq + (size_t)h * 1024 + j);
            acc += d.x * w.x + d.y * w.y + d.z * w.z + d.w * w.w;
        }
#pragma unroll
        for (int o = 16; o > 0; o >>= 1) acc += __shfl_down_sync(0xFFFFFFFFu, acc, o);
        if (lane == 0) g_cbias[b * 1024 + h] = acc + bq[h] + bk[h];
    }
}

// ======================= kernel 2: fp16 HMMA GEMM + fused tanh/Wout score =======================
// R3 mainloop; ONLY change vs R8: empty mbarrier count 8, arrive by lane 0 per warp
// (fewer serialized ATOMS on the mbarrier; producer refills issue earlier).
#define NST 3
#define SMEM_GEMM 98432
__global__ void __launch_bounds__(256, 2) gemm_score_kernel(const float* __restrict__ Wout) {
    extern __shared__ __align__(128) unsigned char smem[];
    const unsigned sb = smem_u32(smem);
    const unsigned OFF_FULL = 98304, OFF_EMPTY = 98336;

    const int tid = threadIdx.x, wid = tid >> 5, lane = tid & 31;
    const int wr = wid >> 1;
    const int wc = wid & 1;
    const int mt = blockIdx.x >> 3;
    const int nc = blockIdx.x & 7;
    const int b = mt >> 4;

    if (tid == 0) {
#pragma unroll
        for (int s = 0; s < NST; s++) {
            MBAR_INIT(sb + OFF_FULL + s * 8, 1);
            MBAR_INIT(sb + OFF_EMPTY + s * 8, 8);   // one arrive per warp
        }
        asm volatile("fence.proxy.async.shared::cta;" ::: "memory");
    }
    __syncthreads();

    const unsigned char* gA = g_encb + (size_t)mt * 262144;
    const unsigned char* gB0 = g_wkb + (size_t)nc * 16384;

    if (tid == 0) {
#pragma unroll
        for (int s = 0; s < NST; s++) {
            MBAR_EXPECT(sb + OFF_FULL + s * 8, 32768);
            bulk_g2s(sb + s * 32768, gA + (size_t)s * 16384, 16384, sb + OFF_FULL + s * 8);
            bulk_g2s(sb + s * 32768 + 16384, gB0 + (size_t)s * 131072, 16384,
                     sb + OFF_FULL + s * 8);
        }
    }

    float acc[2][8][4];
#pragma unroll
    for (int mf = 0; mf < 2; mf++)
#pragma unroll
        for (int nf = 0; nf < 8; nf++)
#pragma unroll
            for (int e = 0; e < 4; e++) acc[mf][nf][e] = 0.f;

    int phF0 = 0, phF1 = 0, phF2 = 0, phE0 = 0, phE1 = 0, phE2 = 0;
    const int l15 = lane & 15;
    const int lhi = lane >> 4;

#pragma unroll 1
    for (int k = 0; k < 16; k++) {
        const int st = k % NST;
        const unsigned fullb = sb + OFF_FULL + st * 8;
        const unsigned emptyb = sb + OFF_EMPTY + st * 8;
        int phF = (st == 0) ? phF0 : (st == 1) ? phF1 : phF2;
        mbar_wait(fullb, phF);
        if (st == 0) phF0 ^= 1; else if (st == 1) phF1 ^= 1; else phF2 ^= 1;

        const unsigned sA = sb + st * 32768;
        const unsigned sB = sA + 16384;

#pragma unroll
        for (int ks = 0; ks < 4; ks++) {
            const unsigned kb = (unsigned)(ks * 32 + lhi * 16);
            unsigned a0[4], a1[4];
            ldsm_x4(a0[0], a0[1], a0[2], a0[3],
                    sA + sw128((unsigned)((wr * 32 + l15) * 128) + kb));
            ldsm_x4(a1[0], a1[1], a1[2], a1[3],
                    sA + sw128((unsigned)((wr * 32 + 16 + l15) * 128) + kb));
            unsigned bf[4][4];
#pragma unroll
            for (int nb = 0; nb < 4; nb++)
                ldsm_x4(bf[nb][0], bf[nb][1], bf[nb][2], bf[nb][3],
                        sB + sw128((unsigned)((wc * 64 + nb * 16 + l15) * 128) + kb));
#pragma unroll
            for (int nb = 0; nb < 4; nb++) {
                mma16816(acc[0][2 * nb], a0[0], a0[1], a0[2], a0[3], bf[nb][0], bf[nb][2]);
                mma16816(acc[0][2 * nb + 1], a0[0], a0[1], a0[2], a0[3], bf[nb][1], bf[nb][3]);
                mma16816(acc[1][2 * nb], a1[0], a1[1], a1[2], a1[3], bf[nb][0], bf[nb][2]);
                mma16816(acc[1][2 * nb + 1], a1[0], a1[1], a1[2], a1[3], bf[nb][1], bf[nb][3]);
            }
        }

        if (lane == 0) MBAR_ARRIVE(emptyb);   // warp-level arrive (ldsm is warp-synchronous)
        if (tid == 0 && k + NST < 16) {
            int phE = (st == 0) ? phE0 : (st == 1) ? phE1 : phE2;
            mbar_wait(emptyb, phE);
            if (st == 0) phE0 ^= 1; else if (st == 1) phE1 ^= 1; else phE2 ^= 1;
            MBAR_EXPECT(fullb, 32768);
            bulk_g2s(sA, gA + (size_t)(k + NST) * 16384, 16384, fullb);
            bulk_g2s(sB, gB0 + (size_t)(k + NST) * 131072, 16384, fullb);
        }
    }

    const int lq = lane & 3, lr = lane >> 2;
    float p[2][2] = {{0.f, 0.f}, {0.f, 0.f}};
#pragma unroll
    for (int nf = 0; nf < 8; nf++) {
        const int col = nc * 128 + wc * 64 + nf * 8 + lq * 2;
        const float2 c01 = __ldg(reinterpret_cast<const float2*>(&g_cbias[b * 1024 + col]));
        const float2 w01 = __ldg(reinterpret_cast<const float2*>(&Wout[col]));
#pragma unroll
        for (int mf = 0; mf < 2; mf++)
#pragma unroll
            for (int h = 0; h < 2; h++) {
                p[mf][h] += tanh_fast(acc[mf][nf][h * 2 + 0] + c01.x) * w01.x +
                            tanh_fast(acc[mf][nf][h * 2 + 1] + c01.y) * w01.y;
            }
    }
#pragma unroll
    for (int mf = 0; mf < 2; mf++)
#pragma unroll
        for (int h = 0; h < 2; h++) {
            float v = p[mf][h];
            v += __shfl_xor_sync(0xFFFFFFFFu, v, 1);
            v += __shfl_xor_sync(0xFFFFFFFFu, v, 2);
            if (lq == 0)
                red_add(&g_scores[mt * 128 + wr * 32 + mf * 16 + h * 8 + lr], v);
        }
}

// ======================= kernel 3: softmax over T=2048 per batch (in place) =======================
__global__ void __launch_bounds__(256) softmax_kernel() {
    __shared__ float red[256];
    int b = blockIdx.x, tid = threadIdx.x;
    float v[8];
    float mx = -1e30f;
#pragma unroll
    for (int i = 0; i < 8; i++) {
        v[i] = g_scores[b * 2048 + tid + i * 256];
        mx = fmaxf(mx, v[i]);
    }
    red[tid] = mx;
    __syncthreads();
    for (int s = 128; s > 0; s >>= 1) {
        if (tid < s) red[tid] = fmaxf(red[tid], red[tid + s]);
        __syncthreads();
    }
    mx = red[0];
    __syncthreads();
    float sum = 0.f;
#pragma unroll
    for (int i = 0; i < 8; i++) {
        v[i] = __expf(v[i] - mx);
        sum += v[i];
    }
    red[tid] = sum;
    __syncthreads();
    for (int s = 128; s > 0; s >>= 1) {
        if (tid < s) red[tid] += red[tid + s];
        __syncthreads();
    }
    float inv = 1.0f / red[0];
#pragma unroll
    for (int i = 0; i < 8; i++) g_scores[b * 2048 + tid + i * 256] = v[i] * inv;
}

// ======================= kernel 4: context (uint4 loads) -> red.add into out =======================
// grid (32 b, 16 kc, 4 ts): each block handles 4 M-tiles (512 tokens) x 64 h values.
__global__ void __launch_bounds__(256) ctx_kernel(float* __restrict__ out) {
    __shared__ float attn_s[512];
    __shared__ float sacc[8][64];
    const int b = blockIdx.x, kc = blockIdx.y, ts = blockIdx.z;
    const int tid = threadIdx.x, w = tid >> 5, l = tid & 31;
    const int lo = l & 7, lr = l >> 3;

    if (tid < 128)
        reinterpret_cast<float4*>(attn_s)[tid] =
            reinterpret_cast<const float4*>(g_scores + b * 2048 + ts * 512)[tid];
    __syncthreads();

    float acc[8];
#pragma unroll
    for (int j = 0; j < 8; j++) acc[j] = 0.f;

#pragma unroll
    for (int i = 0; i < 4; i++) {
        const unsigned char* tb =
            g_encb + (((size_t)(b * 16 + ts * 4 + i)) * 16 + kc) * 16384;
#pragma unroll
        for (int rc = 0; rc < 4; rc++) {
            const int r = rc * 32 + w * 4 + lr;
            const unsigned off = sw128((unsigned)(r * 128 + lo * 16));
            const uint4 v = *reinterpret_cast<const uint4*>(tb + off);
            const float a = attn_s[i * 128 + r];
            const float2 e0 = __half22float2(*reinterpret_cast<const __half2*>(&v.x));
            const float2 e1 = __half22float2(*reinterpret_cast<const __half2*>(&v.y));
            const float2 e2 = __half22float2(*reinterpret_cast<const __half2*>(&v.z));
            const float2 e3 = __half22float2(*reinterpret_cast<const __half2*>(&v.w));
            acc[0] += a * e0.x; acc[1] += a * e0.y;
            acc[2] += a * e1.x; acc[3] += a * e1.y;
            acc[4] += a * e2.x; acc[5] += a * e2.y;
            acc[6] += a * e3.x; acc[7] += a * e3.y;
        }
    }

#pragma unroll
    for (int j = 0; j < 8; j++) {
        acc[j] += __shfl_xor_sync(0xFFFFFFFFu, acc[j], 8);
        acc[j] += __shfl_xor_sync(0xFFFFFFFFu, acc[j], 16);
    }
    if (l < 8) {
#pragma unroll
        for (int j = 0; j < 8; j++) sacc[w][lo * 8 + j] = acc[j];
    }
    __syncthreads();
    if (tid < 64) {
        float s = 0.f;
#pragma unroll
        for (int ww = 0; ww < 8; ww++) s += sacc[ww][tid];
        red_add(&out[b * 1024 + kc * 64 + tid], s);
    }
}

// ======================= launch =======================
extern "C" void kernel_launch(void* const* d_in, const int* in_sizes, int n_in,
                              void* d_out, int out_size) {
    const float* enc  = (const float*)d_in[0];
    const float* dec  = (const float*)d_in[1];
    const float* Wk   = (const float*)d_in[2];
    const float* bk   = (const float*)d_in[3];
    const float* Wq   = (const float*)d_in[4];
    const float* bq   = (const float*)d_in[5];
    const float* Wout = (const float*)d_in[6];
    // d_in[7] = bout: constant shift, cancels in softmax. d_in[8] unused.
    float* out = (float*)d_out;

    static int cfg_done = 0;
    if (!cfg_done) {
        cudaFuncSetAttribute(gemm_score_kernel,
                             cudaFuncAttributeMaxDynamicSharedMemorySize, SMEM_GEMM);
        cfg_done = 1;
    }

    prep_kernel<<<6208, 256>>>(enc, Wk, dec, Wq, bq, bk, out);
    gemm_score_kernel<<<4096, 256, SMEM_GEMM>>>(Wout);
    softmax_kernel<<<32, 256>>>();
    ctx_kernel<<<dim3(32, 16, 4), 256>>>(out);
}